// round 5
// baseline (speedup 1.0000x reference)
#include <cuda_runtime.h>
#include <cuda_bf16.h>
#include <math.h>
#include <stdint.h>

#define N_NODES 100000
#define N_EDGES 1600000
#define DIN 512
#define DH 128
#define DOUT 40
#define TOT_EDGES (N_EDGES + N_NODES)

// ---------------- scratch (device globals; no runtime allocation) -------------
__device__ int   g_deg[N_NODES];
__device__ int   g_off[N_NODES + 1];
__device__ int   g_cur[N_NODES];
__device__ float g_dinv[N_NODES];
__device__ int   g_csr_src[TOT_EDGES];                        // src only (4B/edge)
__device__ __align__(16) float g_h1[(size_t)N_NODES * DH];    // X @ W1 (pre-agg)
__device__ __align__(16) float g_h2[(size_t)N_NODES * DOUT];  // a1 @ W2 (pre-agg)
__device__ __align__(16) float g_w1t[(size_t)DH * DIN];       // W1^T tf32-rounded, [n][k]
__device__ __align__(16) float g_w2t[(size_t)DOUT * DH];      // W2^T tf32-rounded, [n][k]

// ---------------- helpers -------------------------------------------------------
__device__ __forceinline__ float tf32r(float x) {
    uint32_t u;
    asm("cvt.rna.tf32.f32 %0, %1;" : "=r"(u) : "f"(x));
    return __uint_as_float(u);
}

__device__ __forceinline__ void mma_tf32(float* c, const uint32_t* a, uint32_t b0, uint32_t b1) {
    asm volatile(
        "mma.sync.aligned.m16n8k8.row.col.f32.tf32.tf32.f32 "
        "{%0,%1,%2,%3}, {%4,%5,%6,%7}, {%8,%9}, {%0,%1,%2,%3};"
        : "+f"(c[0]), "+f"(c[1]), "+f"(c[2]), "+f"(c[3])
        : "r"(a[0]), "r"(a[1]), "r"(a[2]), "r"(a[3]), "r"(b0), "r"(b1));
}

// ---------------- degree init / histogram -------------------------------------
__global__ void init_kernel() {
    int i = blockIdx.x * blockDim.x + threadIdx.x;
    if (i < N_NODES) g_deg[i] = 1;   // 1 = self-loop
}

__global__ void hist_kernel(const int* __restrict__ dst) {
    int e = blockIdx.x * blockDim.x + threadIdx.x;
    if (e < N_EDGES) atomicAdd(&g_deg[dst[e]], 1);
}

// ---------------- W^T tf32 precompute (fused W1 + W2) ---------------------------
// blockIdx.y < 16: W1 [512][128] -> g_w1t [128][512] (32x32 transpose tiles)
// blockIdx.y == 16 (x==0): W2 [128][40] -> g_w2t [40][128]
__global__ void wt_kernel(const float* __restrict__ W1, const float* __restrict__ W2) {
    if (blockIdx.y < 16) {
        __shared__ float t[32][33];
        const int n0 = blockIdx.x * 32, k0 = blockIdx.y * 32;
        t[threadIdx.y][threadIdx.x] = W1[(size_t)(k0 + threadIdx.y) * DH + n0 + threadIdx.x];
        __syncthreads();
        float v = t[threadIdx.x][threadIdx.y];
        g_w1t[(size_t)(n0 + threadIdx.y) * DIN + k0 + threadIdx.x] = tf32r(v);
    } else if (blockIdx.x == 0) {
        int tid = threadIdx.y * 32 + threadIdx.x;
        for (int idx = tid; idx < DH * DOUT; idx += 1024) {
            int k = idx / DOUT, n = idx % DOUT;
            g_w2t[(size_t)n * DH + k] = tf32r(W2[idx]);
        }
    }
}

// single-block exclusive scan of g_deg -> g_off (+ g_cur), plus dinv = rsqrt(deg)
__global__ void scan_kernel() {
    __shared__ int wsum[32];
    __shared__ int chunk_total;
    const int tid = threadIdx.x;
    const int lane = tid & 31, wp = tid >> 5;
    int carry = 0;
    for (int base = 0; base < N_NODES; base += 1024) {
        int i = base + tid;
        int v = (i < N_NODES) ? g_deg[i] : 0;
        int x = v;
        #pragma unroll
        for (int o = 1; o < 32; o <<= 1) {
            int t = __shfl_up_sync(0xffffffffu, x, o);
            if (lane >= o) x += t;
        }
        if (lane == 31) wsum[wp] = x;
        __syncthreads();
        if (wp == 0) {
            int s = wsum[lane];
            int y = s;
            #pragma unroll
            for (int o = 1; o < 32; o <<= 1) {
                int t = __shfl_up_sync(0xffffffffu, y, o);
                if (lane >= o) y += t;
            }
            wsum[lane] = y - s;
            if (lane == 31) chunk_total = y;
        }
        __syncthreads();
        int incl = x + wsum[wp];
        if (i < N_NODES) {
            int off = carry + incl - v;
            g_off[i] = off;
            g_cur[i] = off;
            g_dinv[i] = rsqrtf((float)v);
        }
        carry += chunk_total;
        __syncthreads();
    }
    if (tid == 0) g_off[N_NODES] = carry;
}

__global__ void scatter_kernel(const int* __restrict__ src, const int* __restrict__ dst) {
    int e = blockIdx.x * blockDim.x + threadIdx.x;
    if (e >= TOT_EDGES) return;
    int s, d;
    if (e < N_EDGES) { s = src[e]; d = dst[e]; }
    else             { s = d = e - N_EDGES; }
    int pos = atomicAdd(&g_cur[d], 1);
    g_csr_src[pos] = s;
}

// ---------------- GEMM1: H1 = X @ W1 via mma.sync tf32 --------------------------
// CTA: 128 rows x 128 cols, K in 16 chunks of 32. 256 threads = 8 warps (4M x 2N).
__global__ __launch_bounds__(256) void gemm1_tf32_kernel(const float* __restrict__ X,
                                                         float* __restrict__ H) {
    __shared__ __align__(16) float sA[128 * 36];   // [row][k] pad 36
    __shared__ __align__(16) float sB[128 * 36];   // [n][k]   pad 36

    const int tid  = threadIdx.x;
    const int row0 = blockIdx.x * 128;

    float4 xr[4], br[4];
    // prologue (chunk 0)
    #pragma unroll
    for (int i = 0; i < 4; i++) {
        int idx = tid + i * 256, row = idx >> 3, kq = idx & 7;
        int gr = row0 + row;
        xr[i] = (gr < N_NODES)
            ? *reinterpret_cast<const float4*>(X + (size_t)gr * DIN + kq * 4)
            : make_float4(0.f, 0.f, 0.f, 0.f);
        br[i] = *reinterpret_cast<const float4*>(g_w1t + (size_t)row * DIN + kq * 4);
    }

    const int wid = tid >> 5, lane = tid & 31;
    const int wm = wid & 3, wn = wid >> 2;
    const int g = lane >> 2, tg = lane & 3;

    float acc[2][8][4];
    #pragma unroll
    for (int a = 0; a < 2; a++)
        #pragma unroll
        for (int b = 0; b < 8; b++)
            #pragma unroll
            for (int c = 0; c < 4; c++) acc[a][b][c] = 0.f;

    #pragma unroll 1
    for (int c = 0; c < DIN / 32; c++) {
        // store staged regs (A converted to tf32)
        #pragma unroll
        for (int i = 0; i < 4; i++) {
            int idx = tid + i * 256, row = idx >> 3, kq = idx & 7;
            float4 v = xr[i];
            v.x = tf32r(v.x); v.y = tf32r(v.y); v.z = tf32r(v.z); v.w = tf32r(v.w);
            *reinterpret_cast<float4*>(sA + row * 36 + kq * 4) = v;
            *reinterpret_cast<float4*>(sB + row * 36 + kq * 4) = br[i];
        }
        __syncthreads();

        // prefetch next chunk
        if (c + 1 < DIN / 32) {
            const int k0 = (c + 1) * 32;
            #pragma unroll
            for (int i = 0; i < 4; i++) {
                int idx = tid + i * 256, row = idx >> 3, kq = idx & 7;
                int gr = row0 + row;
                xr[i] = (gr < N_NODES)
                    ? *reinterpret_cast<const float4*>(X + (size_t)gr * DIN + k0 + kq * 4)
                    : make_float4(0.f, 0.f, 0.f, 0.f);
                br[i] = *reinterpret_cast<const float4*>(g_w1t + (size_t)row * DIN + k0 + kq * 4);
            }
        }

        // MMAs over this chunk: 4 k8 tiles
        #pragma unroll
        for (int kt = 0; kt < 4; kt++) {
            const int kk = kt * 8;
            uint32_t a[2][4];
            #pragma unroll
            for (int mt = 0; mt < 2; mt++) {
                const float* pa = sA + (wm * 32 + mt * 16 + g) * 36 + kk + tg;
                a[mt][0] = __float_as_uint(pa[0]);
                a[mt][1] = __float_as_uint(pa[8 * 36]);
                a[mt][2] = __float_as_uint(pa[4]);
                a[mt][3] = __float_as_uint(pa[8 * 36 + 4]);
            }
            #pragma unroll
            for (int nt = 0; nt < 8; nt++) {
                const float* pb = sB + (wn * 64 + nt * 8 + g) * 36 + kk + tg;
                uint32_t b0 = __float_as_uint(pb[0]);
                uint32_t b1 = __float_as_uint(pb[4]);
                mma_tf32(acc[0][nt], a[0], b0, b1);
                mma_tf32(acc[1][nt], a[1], b0, b1);
            }
        }
        __syncthreads();
    }

    // epilogue
    #pragma unroll
    for (int mt = 0; mt < 2; mt++) {
        int r0 = row0 + wm * 32 + mt * 16 + g;
        #pragma unroll
        for (int nt = 0; nt < 8; nt++) {
            int colb = wn * 64 + nt * 8 + tg * 2;
            if (r0 < N_NODES)
                *reinterpret_cast<float2*>(H + (size_t)r0 * DH + colb) =
                    make_float2(acc[mt][nt][0], acc[mt][nt][1]);
            if (r0 + 8 < N_NODES)
                *reinterpret_cast<float2*>(H + (size_t)(r0 + 8) * DH + colb) =
                    make_float2(acc[mt][nt][2], acc[mt][nt][3]);
        }
    }
}

// ---------------- Fused: a1 = relu(agg(h1)+b1) (smem) then h2 = a1 @ W2 ----------
// 256 threads = 8 warps. Each warp aggregates rows [wid*16, wid*16+16) into sA
// (its own M16 MMA tile -> warp-private, __syncwarp only), then tf32 MMA vs W2^T.
#define G2_SMEM ((128 * 132 + 40 * 132) * 4)
__global__ __launch_bounds__(256) void gemm2_fused_kernel(const float* __restrict__ b1) {
    extern __shared__ float s2[];
    float* sA = s2;                 // [128][132] tf32(a1) tile
    float* sB = s2 + 128 * 132;     // [40][132]  W2^T
    const int tid  = threadIdx.x;
    const int wid  = tid >> 5, lane = tid & 31;
    const int row0 = blockIdx.x * 128;

    // load W2^T into sB (1280 float4 over 256 threads)
    #pragma unroll
    for (int i = 0; i < 5; i++) {
        int idx = tid + i * 256, row = idx >> 5, kq = idx & 31;
        *reinterpret_cast<float4*>(sB + row * 132 + kq * 4) =
            *reinterpret_cast<const float4*>(g_w2t + (size_t)row * DH + kq * 4);
    }

    // phase 1: aggregate 16 nodes per warp
    float4 bv = *reinterpret_cast<const float4*>(b1 + lane * 4);
    #pragma unroll 1
    for (int i = 0; i < 16; i++) {
        const int local = wid * 16 + i;
        const int node  = row0 + local;
        float4 acc = make_float4(0.f, 0.f, 0.f, 0.f);
        if (node < N_NODES) {
            const int beg = g_off[node], end = g_off[node + 1];
            const float dvd = g_dinv[node];
            int s0 = g_csr_src[beg];
            #pragma unroll 1
            for (int p = beg; p < end; p++) {
                int s = s0;
                if (p + 1 < end) s0 = g_csr_src[p + 1];
                float w = g_dinv[s] * dvd;
                float4 hv = *reinterpret_cast<const float4*>(g_h1 + (size_t)s * DH + lane * 4);
                acc.x += w * hv.x; acc.y += w * hv.y;
                acc.z += w * hv.z; acc.w += w * hv.w;
            }
            acc.x = tf32r(fmaxf(acc.x + bv.x, 0.f));
            acc.y = tf32r(fmaxf(acc.y + bv.y, 0.f));
            acc.z = tf32r(fmaxf(acc.z + bv.z, 0.f));
            acc.w = tf32r(fmaxf(acc.w + bv.w, 0.f));
        }
        *reinterpret_cast<float4*>(sA + local * 132 + lane * 4) = acc;
    }
    __syncwarp();
    __syncthreads();   // sB visibility (and sA, conservatively)

    // phase 2: warp wid handles M16 tile rows [wid*16, +16), 5 N8 tiles
    const int g = lane >> 2, tg = lane & 3;
    float acc2[5][4];
    #pragma unroll
    for (int b = 0; b < 5; b++)
        #pragma unroll
        for (int c = 0; c < 4; c++) acc2[b][c] = 0.f;

    #pragma unroll
    for (int kt = 0; kt < DH / 8; kt++) {
        const int kk = kt * 8;
        const float* pa = sA + (wid * 16 + g) * 132 + kk + tg;
        uint32_t a[4];
        a[0] = __float_as_uint(pa[0]);
        a[1] = __float_as_uint(pa[8 * 132]);
        a[2] = __float_as_uint(pa[4]);
        a[3] = __float_as_uint(pa[8 * 132 + 4]);
        #pragma unroll
        for (int nt = 0; nt < 5; nt++) {
            const float* pb = sB + (nt * 8 + g) * 132 + kk + tg;
            uint32_t b0 = __float_as_uint(pb[0]);
            uint32_t b1 = __float_as_uint(pb[4]);
            mma_tf32(acc2[nt], a, b0, b1);
        }
    }

    const int r0 = row0 + wid * 16 + g;
    #pragma unroll
    for (int nt = 0; nt < 5; nt++) {
        int colb = nt * 8 + tg * 2;
        if (r0 < N_NODES)
            *reinterpret_cast<float2*>(g_h2 + (size_t)r0 * DOUT + colb) =
                make_float2(acc2[nt][0], acc2[nt][1]);
        if (r0 + 8 < N_NODES)
            *reinterpret_cast<float2*>(g_h2 + (size_t)(r0 + 8) * DOUT + colb) =
                make_float2(acc2[nt][2], acc2[nt][3]);
    }
}

// ---------------- Agg2 + b2 + log_softmax fused, warp per node -------------------
__global__ void agg2_lsm_kernel(const float* __restrict__ b2, float* __restrict__ out,
                                int do_lsm) {
    int gw = (blockIdx.x * blockDim.x + threadIdx.x) >> 5;
    int lane = threadIdx.x & 31;
    if (gw >= N_NODES) return;
    const int beg = g_off[gw], end = g_off[gw + 1];
    const float dvd = g_dinv[gw];
    float acc0 = 0.f, acc1 = 0.f;
    bool has2 = lane < (DOUT - 32);
    int s0 = g_csr_src[beg];
    for (int p = beg; p < end; p++) {
        int s = s0;
        if (p + 1 < end) s0 = g_csr_src[p + 1];
        float w = g_dinv[s] * dvd;
        const float* row = g_h2 + (size_t)s * DOUT;
        acc0 += w * row[lane];
        if (has2) acc1 += w * row[32 + lane];
    }
    acc0 += b2[lane];
    if (has2) acc1 += b2[32 + lane];

    float* orow = out + (size_t)gw * DOUT;
    orow[lane] = acc0;
    if (has2) orow[32 + lane] = acc1;

    if (do_lsm) {
        float m = fmaxf(acc0, has2 ? acc1 : -INFINITY);
        #pragma unroll
        for (int o = 16; o > 0; o >>= 1) m = fmaxf(m, __shfl_xor_sync(0xffffffffu, m, o));
        float e = expf(acc0 - m) + (has2 ? expf(acc1 - m) : 0.f);
        #pragma unroll
        for (int o = 16; o > 0; o >>= 1) e += __shfl_xor_sync(0xffffffffu, e, o);
        float lse = m + logf(e);
        float* lrow = out + (size_t)N_NODES * DOUT + (size_t)gw * DOUT;
        lrow[lane] = acc0 - lse;
        if (has2) lrow[32 + lane] = acc1 - lse;
    }
}

// ---------------- launch --------------------------------------------------------
extern "C" void kernel_launch(void* const* d_in, const int* in_sizes, int n_in,
                              void* d_out, int out_size) {
    const float* x   = (const float*)d_in[0];
    const int*   ei  = (const int*)  d_in[1];   // [2,E] row-major
    const float* W1  = (const float*)d_in[2];
    const float* b1  = (const float*)d_in[3];
    const float* W2  = (const float*)d_in[4];
    const float* b2  = (const float*)d_in[5];
    float* out = (float*)d_out;

    const int* src = ei;
    const int* dst = ei + N_EDGES;

    float* h1;  cudaGetSymbolAddress((void**)&h1, g_h1);

    cudaFuncSetAttribute(gemm2_fused_kernel, cudaFuncAttributeMaxDynamicSharedMemorySize,
                         G2_SMEM);

    // order chosen so gemm1 is the 4th launch (gets profiled by the fixed -s window)
    init_kernel<<<(N_NODES + 255) / 256, 256>>>();                       // 1
    hist_kernel<<<(N_EDGES + 255) / 256, 256>>>(dst);                    // 2
    wt_kernel<<<dim3(4, 17), dim3(32, 32)>>>(W1, W2);                    // 3
    gemm1_tf32_kernel<<<(N_NODES + 127) / 128, 256>>>(x, h1);            // 4 <- profile
    scan_kernel<<<1, 1024>>>();                                          // 5
    scatter_kernel<<<(TOT_EDGES + 255) / 256, 256>>>(src, dst);          // 6
    gemm2_fused_kernel<<<(N_NODES + 127) / 128, 256, G2_SMEM>>>(b1);     // 7
    int do_lsm = (out_size >= 2 * N_NODES * DOUT) ? 1 : 0;
    agg2_lsm_kernel<<<(N_NODES * 32 + 255) / 256, 256>>>(b2, out, do_lsm); // 8
}

// round 6
// speedup vs baseline: 1.3456x; 1.3456x over previous
#include <cuda_runtime.h>
#include <cuda_bf16.h>
#include <math.h>
#include <stdint.h>

#define N_NODES 100000
#define N_EDGES 1600000
#define DIN 512
#define DH 128
#define DOUT 40
#define TOT_EDGES (N_EDGES + N_NODES)

// ---------------- scratch (device globals; no runtime allocation) -------------
__device__ int   g_deg[N_NODES];
__device__ int   g_off[N_NODES + 1];
__device__ int   g_cur[N_NODES];
__device__ float g_dinv[N_NODES];
__device__ __align__(16) int2  g_csr[TOT_EDGES];              // (src, w bits)
__device__ __align__(16) float g_h1[(size_t)N_NODES * DH];    // X @ W1 (pre-agg)
__device__ __align__(16) float g_a1[(size_t)N_NODES * DH];    // relu(agg(h1)+b1)
__device__ __align__(16) float g_h2[(size_t)N_NODES * DOUT];  // a1 @ W2 (pre-agg)
__device__ __align__(16) float g_w1t[(size_t)DH * DIN];       // W1^T tf32(RNA), [n][k]
__device__ __align__(16) float g_w2t[(size_t)DOUT * DH];      // W2^T tf32(RNA), [n][k]

// ---------------- helpers -------------------------------------------------------
__device__ __forceinline__ uint32_t smem_u32(const void* p) {
    uint32_t a;
    asm("{ .reg .u64 t; cvta.to.shared.u64 t, %1; cvt.u32.u64 %0, t; }" : "=r"(a) : "l"(p));
    return a;
}

__device__ __forceinline__ float tf32r(float x) {
    uint32_t u;
    asm("cvt.rna.tf32.f32 %0, %1;" : "=r"(u) : "f"(x));
    return __uint_as_float(u);
}

__device__ __forceinline__ uint32_t tf32u(float x) {
    uint32_t u;
    asm("cvt.rna.tf32.f32 %0, %1;" : "=r"(u) : "f"(x));
    return u;
}

__device__ __forceinline__ void mma_tf32(float* c, const uint32_t* a, uint32_t b0, uint32_t b1) {
    asm volatile(
        "mma.sync.aligned.m16n8k8.row.col.f32.tf32.tf32.f32 "
        "{%0,%1,%2,%3}, {%4,%5,%6,%7}, {%8,%9}, {%0,%1,%2,%3};"
        : "+f"(c[0]), "+f"(c[1]), "+f"(c[2]), "+f"(c[3])
        : "r"(a[0]), "r"(a[1]), "r"(a[2]), "r"(a[3]), "r"(b0), "r"(b1));
}

// ---------------- degree init / histogram -------------------------------------
__global__ void init_kernel() {
    int i = blockIdx.x * blockDim.x + threadIdx.x;
    if (i < N_NODES) g_deg[i] = 1;   // 1 = self-loop
}

__global__ void hist_kernel(const int* __restrict__ dst) {
    int e = blockIdx.x * blockDim.x + threadIdx.x;
    if (e < N_EDGES) atomicAdd(&g_deg[dst[e]], 1);
}

// ---------------- W^T tf32 precompute (fused W1 + W2) ---------------------------
__global__ void wt_kernel(const float* __restrict__ W1, const float* __restrict__ W2) {
    if (blockIdx.y < 16) {
        __shared__ float t[32][33];
        const int n0 = blockIdx.x * 32, k0 = blockIdx.y * 32;
        t[threadIdx.y][threadIdx.x] = W1[(size_t)(k0 + threadIdx.y) * DH + n0 + threadIdx.x];
        __syncthreads();
        float v = t[threadIdx.x][threadIdx.y];
        g_w1t[(size_t)(n0 + threadIdx.y) * DIN + k0 + threadIdx.x] = tf32r(v);
    } else if (blockIdx.x == 0) {
        int tid = threadIdx.y * 32 + threadIdx.x;
        for (int idx = tid; idx < DH * DOUT; idx += 1024) {
            int k = idx / DOUT, n = idx % DOUT;
            g_w2t[(size_t)n * DH + k] = tf32r(W2[idx]);
        }
    }
}

// single-block exclusive scan of g_deg -> g_off (+ g_cur), plus dinv = rsqrt(deg)
__global__ void scan_kernel() {
    __shared__ int wsum[32];
    __shared__ int chunk_total;
    const int tid = threadIdx.x;
    const int lane = tid & 31, wp = tid >> 5;
    int carry = 0;
    for (int base = 0; base < N_NODES; base += 1024) {
        int i = base + tid;
        int v = (i < N_NODES) ? g_deg[i] : 0;
        int x = v;
        #pragma unroll
        for (int o = 1; o < 32; o <<= 1) {
            int t = __shfl_up_sync(0xffffffffu, x, o);
            if (lane >= o) x += t;
        }
        if (lane == 31) wsum[wp] = x;
        __syncthreads();
        if (wp == 0) {
            int s = wsum[lane];
            int y = s;
            #pragma unroll
            for (int o = 1; o < 32; o <<= 1) {
                int t = __shfl_up_sync(0xffffffffu, y, o);
                if (lane >= o) y += t;
            }
            wsum[lane] = y - s;
            if (lane == 31) chunk_total = y;
        }
        __syncthreads();
        int incl = x + wsum[wp];
        if (i < N_NODES) {
            int off = carry + incl - v;
            g_off[i] = off;
            g_cur[i] = off;
            g_dinv[i] = rsqrtf((float)v);
        }
        carry += chunk_total;
        __syncthreads();
    }
    if (tid == 0) g_off[N_NODES] = carry;
}

__global__ void scatter_kernel(const int* __restrict__ src, const int* __restrict__ dst) {
    int e = blockIdx.x * blockDim.x + threadIdx.x;
    if (e >= TOT_EDGES) return;
    int s, d;
    if (e < N_EDGES) { s = src[e]; d = dst[e]; }
    else             { s = d = e - N_EDGES; }
    int pos = atomicAdd(&g_cur[d], 1);
    g_csr[pos] = make_int2(s, __float_as_int(g_dinv[s] * g_dinv[d]));
}

// ---------------- GEMM1: H1 = X @ W1, tf32 MMA + 3-stage cp.async pipeline -------
#define NCH 16
#define STAGES 3
#define A_STRIDE 36                            // floats per row (pad 32 -> 36)
#define TILE_BYTES (128 * A_STRIDE * 4)        // 18432
#define STAGE_BYTES (2 * TILE_BYTES)           // A + B
#define G1_SMEM (STAGES * STAGE_BYTES)         // 110592

__global__ __launch_bounds__(256) void gemm1_tf32_kernel(const float* __restrict__ X,
                                                         float* __restrict__ H) {
    extern __shared__ float s1[];
    const uint32_t sbase = smem_u32(s1);
    const int tid  = threadIdx.x;
    const int row0 = blockIdx.x * 128;

    const int ldrow = tid >> 3;               // 0..31? no: tid/8 -> 0..31 with j offset
    const int ldkq  = tid & 7;

    // issue cp.async loads for chunk c into its stage buffer
    auto issue = [&](int c) {
        const int s = c % STAGES;
        const uint32_t sa = sbase + s * STAGE_BYTES;
        const uint32_t sb = sa + TILE_BYTES;
        const int k0 = c * 32;
        #pragma unroll
        for (int j = 0; j < 4; j++) {
            const int row = ldrow + j * 32;
            const int gr  = row0 + row;
            const int zn  = (gr < N_NODES) ? 16 : 0;
            const float* ga = X + (size_t)(gr < N_NODES ? gr : 0) * DIN + k0 + ldkq * 4;
            asm volatile("cp.async.cg.shared.global [%0], [%1], 16, %2;"
                         :: "r"(sa + row * (A_STRIDE * 4) + ldkq * 16), "l"(ga), "r"(zn));
            const float* gb = g_w1t + (size_t)row * DIN + k0 + ldkq * 4;
            asm volatile("cp.async.cg.shared.global [%0], [%1], 16;"
                         :: "r"(sb + row * (A_STRIDE * 4) + ldkq * 16), "l"(gb));
        }
    };

    issue(0);
    asm volatile("cp.async.commit_group;" ::: "memory");
    issue(1);
    asm volatile("cp.async.commit_group;" ::: "memory");

    const int wid = tid >> 5, lane = tid & 31;
    const int wm = wid & 3, wn = wid >> 2;
    const int g = lane >> 2, tg = lane & 3;

    float acc[2][8][4];
    #pragma unroll
    for (int a = 0; a < 2; a++)
        #pragma unroll
        for (int b = 0; b < 8; b++)
            #pragma unroll
            for (int c = 0; c < 4; c++) acc[a][b][c] = 0.f;

    #pragma unroll 1
    for (int c = 0; c < NCH; c++) {
        asm volatile("cp.async.wait_group 1;" ::: "memory");
        __syncthreads();
        if (c + STAGES - 1 < NCH) issue(c + STAGES - 1);
        asm volatile("cp.async.commit_group;" ::: "memory");

        const float* sA = s1 + (size_t)(c % STAGES) * (STAGE_BYTES / 4);
        const float* sB = sA + TILE_BYTES / 4;

        #pragma unroll
        for (int kt = 0; kt < 4; kt++) {
            const int kk = kt * 8;
            uint32_t a[2][4];
            #pragma unroll
            for (int mt = 0; mt < 2; mt++) {
                const float* pa = sA + (wm * 32 + mt * 16 + g) * A_STRIDE + kk + tg;
                a[mt][0] = tf32u(pa[0]);
                a[mt][1] = tf32u(pa[8 * A_STRIDE]);
                a[mt][2] = tf32u(pa[4]);
                a[mt][3] = tf32u(pa[8 * A_STRIDE + 4]);
            }
            #pragma unroll
            for (int nt = 0; nt < 8; nt++) {
                const float* pb = sB + (wn * 64 + nt * 8 + g) * A_STRIDE + kk + tg;
                uint32_t b0 = __float_as_uint(pb[0]);
                uint32_t b1 = __float_as_uint(pb[4]);
                mma_tf32(acc[0][nt], a[0], b0, b1);
                mma_tf32(acc[1][nt], a[1], b0, b1);
            }
        }
    }

    // epilogue
    #pragma unroll
    for (int mt = 0; mt < 2; mt++) {
        int r0 = row0 + wm * 32 + mt * 16 + g;
        #pragma unroll
        for (int nt = 0; nt < 8; nt++) {
            int colb = wn * 64 + nt * 8 + tg * 2;
            if (r0 < N_NODES)
                *reinterpret_cast<float2*>(H + (size_t)r0 * DH + colb) =
                    make_float2(acc[mt][nt][0], acc[mt][nt][1]);
            if (r0 + 8 < N_NODES)
                *reinterpret_cast<float2*>(H + (size_t)(r0 + 8) * DH + colb) =
                    make_float2(acc[mt][nt][2], acc[mt][nt][3]);
        }
    }
}

// ---------------- Agg1: a1 = relu(A_hat @ h1 + b1), warp per node --------------
__global__ void agg1_kernel(const float* __restrict__ b1) {
    int gw = (blockIdx.x * blockDim.x + threadIdx.x) >> 5;
    int lane = threadIdx.x & 31;
    if (gw >= N_NODES) return;
    const int beg = g_off[gw], end = g_off[gw + 1];
    float4 acc = make_float4(0.f, 0.f, 0.f, 0.f);
    int2 e0 = g_csr[beg];
    for (int p = beg; p < end; p++) {
        int2 e = e0;
        if (p + 1 < end) e0 = g_csr[p + 1];
        float w = __int_as_float(e.y);
        float4 hv = *reinterpret_cast<const float4*>(g_h1 + (size_t)e.x * DH + lane * 4);
        acc.x += w * hv.x; acc.y += w * hv.y; acc.z += w * hv.z; acc.w += w * hv.w;
    }
    float4 bv = *reinterpret_cast<const float4*>(b1 + lane * 4);
    acc.x = fmaxf(acc.x + bv.x, 0.f);
    acc.y = fmaxf(acc.y + bv.y, 0.f);
    acc.z = fmaxf(acc.z + bv.z, 0.f);
    acc.w = fmaxf(acc.w + bv.w, 0.f);
    *reinterpret_cast<float4*>(g_a1 + (size_t)gw * DH + lane * 4) = acc;
}

// ---------------- GEMM2: h2 = a1 @ W2 via mma.sync tf32 --------------------------
#define G2_SMEM ((128 * 132 + 40 * 132) * 4)
__global__ __launch_bounds__(128) void gemm2_tf32_kernel() {
    extern __shared__ float s2[];
    float* sA = s2;                 // [128][132]
    float* sB = s2 + 128 * 132;     // [40][132]
    const int tid  = threadIdx.x;
    const int row0 = blockIdx.x * 128;

    #pragma unroll
    for (int i = 0; i < 32; i++) {
        int idx = tid + i * 128, row = idx >> 5, kq = idx & 31;
        int gr = row0 + row;
        float4 v = (gr < N_NODES)
            ? *reinterpret_cast<const float4*>(g_a1 + (size_t)gr * DH + kq * 4)
            : make_float4(0.f, 0.f, 0.f, 0.f);
        v.x = tf32r(v.x); v.y = tf32r(v.y); v.z = tf32r(v.z); v.w = tf32r(v.w);
        *reinterpret_cast<float4*>(sA + row * 132 + kq * 4) = v;
    }
    #pragma unroll
    for (int i = 0; i < 10; i++) {
        int idx = tid + i * 128, row = idx >> 5, kq = idx & 31;
        float4 v = *reinterpret_cast<const float4*>(g_w2t + (size_t)row * DH + kq * 4);
        *reinterpret_cast<float4*>(sB + row * 132 + kq * 4) = v;
    }
    __syncthreads();

    const int wid = tid >> 5, lane = tid & 31;
    const int g = lane >> 2, tg = lane & 3;

    float acc[2][5][4];
    #pragma unroll
    for (int a = 0; a < 2; a++)
        #pragma unroll
        for (int b = 0; b < 5; b++)
            #pragma unroll
            for (int c = 0; c < 4; c++) acc[a][b][c] = 0.f;

    #pragma unroll
    for (int kt = 0; kt < DH / 8; kt++) {
        const int kk = kt * 8;
        uint32_t a[2][4];
        #pragma unroll
        for (int mt = 0; mt < 2; mt++) {
            const float* pa = sA + (wid * 32 + mt * 16 + g) * 132 + kk + tg;
            a[mt][0] = __float_as_uint(pa[0]);
            a[mt][1] = __float_as_uint(pa[8 * 132]);
            a[mt][2] = __float_as_uint(pa[4]);
            a[mt][3] = __float_as_uint(pa[8 * 132 + 4]);
        }
        #pragma unroll
        for (int nt = 0; nt < 5; nt++) {
            const float* pb = sB + (nt * 8 + g) * 132 + kk + tg;
            uint32_t b0 = __float_as_uint(pb[0]);
            uint32_t b1 = __float_as_uint(pb[4]);
            mma_tf32(acc[0][nt], a[0], b0, b1);
            mma_tf32(acc[1][nt], a[1], b0, b1);
        }
    }

    #pragma unroll
    for (int mt = 0; mt < 2; mt++) {
        int r0 = row0 + wid * 32 + mt * 16 + g;
        #pragma unroll
        for (int nt = 0; nt < 5; nt++) {
            int colb = nt * 8 + tg * 2;
            if (r0 < N_NODES)
                *reinterpret_cast<float2*>(g_h2 + (size_t)r0 * DOUT + colb) =
                    make_float2(acc[mt][nt][0], acc[mt][nt][1]);
            if (r0 + 8 < N_NODES)
                *reinterpret_cast<float2*>(g_h2 + (size_t)(r0 + 8) * DOUT + colb) =
                    make_float2(acc[mt][nt][2], acc[mt][nt][3]);
        }
    }
}

// ---------------- Agg2 + b2 + log_softmax fused, warp per node -------------------
__global__ void agg2_lsm_kernel(const float* __restrict__ b2, float* __restrict__ out,
                                int do_lsm) {
    int gw = (blockIdx.x * blockDim.x + threadIdx.x) >> 5;
    int lane = threadIdx.x & 31;
    if (gw >= N_NODES) return;
    const int beg = g_off[gw], end = g_off[gw + 1];
    float acc0 = 0.f, acc1 = 0.f;
    bool has2 = lane < (DOUT - 32);
    int2 e0 = g_csr[beg];
    for (int p = beg; p < end; p++) {
        int2 e = e0;
        if (p + 1 < end) e0 = g_csr[p + 1];
        float w = __int_as_float(e.y);
        const float* row = g_h2 + (size_t)e.x * DOUT;
        acc0 += w * row[lane];
        if (has2) acc1 += w * row[32 + lane];
    }
    acc0 += b2[lane];
    if (has2) acc1 += b2[32 + lane];

    float* orow = out + (size_t)gw * DOUT;
    orow[lane] = acc0;
    if (has2) orow[32 + lane] = acc1;

    if (do_lsm) {
        float m = fmaxf(acc0, has2 ? acc1 : -INFINITY);
        #pragma unroll
        for (int o = 16; o > 0; o >>= 1) m = fmaxf(m, __shfl_xor_sync(0xffffffffu, m, o));
        float e = expf(acc0 - m) + (has2 ? expf(acc1 - m) : 0.f);
        #pragma unroll
        for (int o = 16; o > 0; o >>= 1) e += __shfl_xor_sync(0xffffffffu, e, o);
        float lse = m + logf(e);
        float* lrow = out + (size_t)N_NODES * DOUT + (size_t)gw * DOUT;
        lrow[lane] = acc0 - lse;
        if (has2) lrow[32 + lane] = acc1 - lse;
    }
}

// ---------------- launch --------------------------------------------------------
extern "C" void kernel_launch(void* const* d_in, const int* in_sizes, int n_in,
                              void* d_out, int out_size) {
    const float* x   = (const float*)d_in[0];
    const int*   ei  = (const int*)  d_in[1];   // [2,E] row-major
    const float* W1  = (const float*)d_in[2];
    const float* b1  = (const float*)d_in[3];
    const float* W2  = (const float*)d_in[4];
    const float* b2  = (const float*)d_in[5];
    float* out = (float*)d_out;

    const int* src = ei;
    const int* dst = ei + N_EDGES;

    float* h1;  cudaGetSymbolAddress((void**)&h1, g_h1);

    cudaFuncSetAttribute(gemm1_tf32_kernel, cudaFuncAttributeMaxDynamicSharedMemorySize,
                         G1_SMEM);
    cudaFuncSetAttribute(gemm2_tf32_kernel, cudaFuncAttributeMaxDynamicSharedMemorySize,
                         G2_SMEM);

    // gemm1 kept as 4th launch (profiled by the fixed -s window)
    init_kernel<<<(N_NODES + 255) / 256, 256>>>();                         // 1
    hist_kernel<<<(N_EDGES + 255) / 256, 256>>>(dst);                      // 2
    wt_kernel<<<dim3(4, 17), dim3(32, 32)>>>(W1, W2);                      // 3
    gemm1_tf32_kernel<<<(N_NODES + 127) / 128, 256, G1_SMEM>>>(x, h1);     // 4 <- profile
    scan_kernel<<<1, 1024>>>();                                            // 5
    scatter_kernel<<<(TOT_EDGES + 255) / 256, 256>>>(src, dst);            // 6
    agg1_kernel<<<(N_NODES * 32 + 255) / 256, 256>>>(b1);                  // 7
    gemm2_tf32_kernel<<<(N_NODES + 127) / 128, 128, G2_SMEM>>>();          // 8
    int do_lsm = (out_size >= 2 * N_NODES * DOUT) ? 1 : 0;
    agg2_lsm_kernel<<<(N_NODES * 32 + 255) / 256, 256>>>(b2, out, do_lsm); // 9
}

// round 7
// speedup vs baseline: 1.3911x; 1.0339x over previous
#include <cuda_runtime.h>
#include <cuda_bf16.h>
#include <math.h>
#include <stdint.h>

#define N_NODES 100000
#define N_EDGES 1600000
#define DIN 512
#define DH 128
#define DOUT 40
#define TOT_EDGES (N_EDGES + N_NODES)

// ---------------- scratch (device globals; no runtime allocation) -------------
__device__ int   g_deg[N_NODES];
__device__ int   g_off[N_NODES + 1];
__device__ int   g_cur[N_NODES];
__device__ float g_dinv[N_NODES];
__device__ __align__(16) int2  g_csr[TOT_EDGES];              // (src, w bits)
__device__ __align__(16) float g_h1[(size_t)N_NODES * DH];    // X @ W1 (pre-agg)
__device__ __align__(16) float g_a1[(size_t)N_NODES * DH];    // relu(agg(h1)+b1)
__device__ __align__(16) float g_h2[(size_t)N_NODES * DOUT];  // a1 @ W2 (pre-agg)
__device__ __align__(16) float g_w1t[(size_t)DH * DIN];       // W1^T tf32(RNA), [n][k]
__device__ __align__(16) float g_w2t[(size_t)DOUT * DH];      // W2^T tf32(RNA), [n][k]

// ---------------- helpers -------------------------------------------------------
__device__ __forceinline__ uint32_t smem_u32(const void* p) {
    uint32_t a;
    asm("{ .reg .u64 t; cvta.to.shared.u64 t, %1; cvt.u32.u64 %0, t; }" : "=r"(a) : "l"(p));
    return a;
}

__device__ __forceinline__ float tf32r(float x) {
    uint32_t u;
    asm("cvt.rna.tf32.f32 %0, %1;" : "=r"(u) : "f"(x));
    return __uint_as_float(u);
}

__device__ __forceinline__ uint32_t tf32u(float x) {
    uint32_t u;
    asm("cvt.rna.tf32.f32 %0, %1;" : "=r"(u) : "f"(x));
    return u;
}

__device__ __forceinline__ void mma_tf32(float* c, const uint32_t* a, uint32_t b0, uint32_t b1) {
    asm volatile(
        "mma.sync.aligned.m16n8k8.row.col.f32.tf32.tf32.f32 "
        "{%0,%1,%2,%3}, {%4,%5,%6,%7}, {%8,%9}, {%0,%1,%2,%3};"
        : "+f"(c[0]), "+f"(c[1]), "+f"(c[2]), "+f"(c[3])
        : "r"(a[0]), "r"(a[1]), "r"(a[2]), "r"(a[3]), "r"(b0), "r"(b1));
}

// ---------------- degree init / histogram -------------------------------------
__global__ void init_kernel() {
    int i = blockIdx.x * blockDim.x + threadIdx.x;
    if (i < N_NODES) g_deg[i] = 1;   // 1 = self-loop
}

__global__ void hist_kernel(const int* __restrict__ dst) {
    int e = blockIdx.x * blockDim.x + threadIdx.x;
    if (e < N_EDGES) atomicAdd(&g_deg[dst[e]], 1);
}

// ---------------- W^T tf32 precompute (fused W1 + W2) ---------------------------
__global__ void wt_kernel(const float* __restrict__ W1, const float* __restrict__ W2) {
    if (blockIdx.y < 16) {
        __shared__ float t[32][33];
        const int n0 = blockIdx.x * 32, k0 = blockIdx.y * 32;
        t[threadIdx.y][threadIdx.x] = W1[(size_t)(k0 + threadIdx.y) * DH + n0 + threadIdx.x];
        __syncthreads();
        float v = t[threadIdx.x][threadIdx.y];
        g_w1t[(size_t)(n0 + threadIdx.y) * DIN + k0 + threadIdx.x] = tf32r(v);
    } else if (blockIdx.x == 0) {
        int tid = threadIdx.y * 32 + threadIdx.x;
        for (int idx = tid; idx < DH * DOUT; idx += 1024) {
            int k = idx / DOUT, n = idx % DOUT;
            g_w2t[(size_t)n * DH + k] = tf32r(W2[idx]);
        }
    }
}

// single-block exclusive scan of g_deg -> g_off (+ g_cur), plus dinv = rsqrt(deg)
__global__ void scan_kernel() {
    __shared__ int wsum[32];
    __shared__ int chunk_total;
    const int tid = threadIdx.x;
    const int lane = tid & 31, wp = tid >> 5;
    int carry = 0;
    for (int base = 0; base < N_NODES; base += 1024) {
        int i = base + tid;
        int v = (i < N_NODES) ? g_deg[i] : 0;
        int x = v;
        #pragma unroll
        for (int o = 1; o < 32; o <<= 1) {
            int t = __shfl_up_sync(0xffffffffu, x, o);
            if (lane >= o) x += t;
        }
        if (lane == 31) wsum[wp] = x;
        __syncthreads();
        if (wp == 0) {
            int s = wsum[lane];
            int y = s;
            #pragma unroll
            for (int o = 1; o < 32; o <<= 1) {
                int t = __shfl_up_sync(0xffffffffu, y, o);
                if (lane >= o) y += t;
            }
            wsum[lane] = y - s;
            if (lane == 31) chunk_total = y;
        }
        __syncthreads();
        int incl = x + wsum[wp];
        if (i < N_NODES) {
            int off = carry + incl - v;
            g_off[i] = off;
            g_cur[i] = off;
            g_dinv[i] = rsqrtf((float)v);
        }
        carry += chunk_total;
        __syncthreads();
    }
    if (tid == 0) g_off[N_NODES] = carry;
}

__global__ void scatter_kernel(const int* __restrict__ src, const int* __restrict__ dst) {
    int e = blockIdx.x * blockDim.x + threadIdx.x;
    if (e >= TOT_EDGES) return;
    int s, d;
    if (e < N_EDGES) { s = src[e]; d = dst[e]; }
    else             { s = d = e - N_EDGES; }
    int pos = atomicAdd(&g_cur[d], 1);
    g_csr[pos] = make_int2(s, __float_as_int(g_dinv[s] * g_dinv[d]));
}

// ---------------- GEMM1: H1 = X @ W1, tf32 MMA + 3-stage cp.async pipeline -------
#define NCH 16
#define STAGES 3
#define A_STRIDE 36                            // floats per row (pad 32 -> 36)
#define TILE_BYTES (128 * A_STRIDE * 4)        // 18432
#define STAGE_BYTES (2 * TILE_BYTES)           // A + B
#define G1_SMEM (STAGES * STAGE_BYTES)         // 110592

__global__ __launch_bounds__(256) void gemm1_tf32_kernel(const float* __restrict__ X,
                                                         float* __restrict__ H) {
    extern __shared__ float s1[];
    const uint32_t sbase = smem_u32(s1);
    const int tid  = threadIdx.x;
    const int row0 = blockIdx.x * 128;

    const int ldrow = tid >> 3;
    const int ldkq  = tid & 7;

    // issue cp.async loads for chunk c into its stage buffer
    auto issue = [&](int c) {
        const int s = c % STAGES;
        const uint32_t sa = sbase + s * STAGE_BYTES;
        const uint32_t sb = sa + TILE_BYTES;
        const int k0 = c * 32;
        #pragma unroll
        for (int j = 0; j < 4; j++) {
            const int row = ldrow + j * 32;
            const int gr  = row0 + row;
            const int zn  = (gr < N_NODES) ? 16 : 0;
            const float* ga = X + (size_t)(gr < N_NODES ? gr : 0) * DIN + k0 + ldkq * 4;
            asm volatile("cp.async.cg.shared.global [%0], [%1], 16, %2;"
                         :: "r"(sa + row * (A_STRIDE * 4) + ldkq * 16), "l"(ga), "r"(zn));
            const float* gb = g_w1t + (size_t)row * DIN + k0 + ldkq * 4;
            asm volatile("cp.async.cg.shared.global [%0], [%1], 16;"
                         :: "r"(sb + row * (A_STRIDE * 4) + ldkq * 16), "l"(gb));
        }
    };

    issue(0);
    asm volatile("cp.async.commit_group;" ::: "memory");
    issue(1);
    asm volatile("cp.async.commit_group;" ::: "memory");

    const int wid = tid >> 5, lane = tid & 31;
    const int wm = wid & 3, wn = wid >> 2;
    const int g = lane >> 2, tg = lane & 3;

    float acc[2][8][4];
    #pragma unroll
    for (int a = 0; a < 2; a++)
        #pragma unroll
        for (int b = 0; b < 8; b++)
            #pragma unroll
            for (int c = 0; c < 4; c++) acc[a][b][c] = 0.f;

    // fragment loaders
    auto load_a = [&](uint32_t af[2][4], const float* sA, int kt) {
        const int kk = kt * 8;
        #pragma unroll
        for (int mt = 0; mt < 2; mt++) {
            const float* pa = sA + (wm * 32 + mt * 16 + g) * A_STRIDE + kk + tg;
            af[mt][0] = tf32u(pa[0]);
            af[mt][1] = tf32u(pa[8 * A_STRIDE]);
            af[mt][2] = tf32u(pa[4]);
            af[mt][3] = tf32u(pa[8 * A_STRIDE + 4]);
        }
    };
    auto load_b = [&](uint32_t bf[8][2], const float* sB, int kt) {
        const int kk = kt * 8;
        #pragma unroll
        for (int nt = 0; nt < 8; nt++) {
            const float* pb = sB + (wn * 64 + nt * 8 + g) * A_STRIDE + kk + tg;
            bf[nt][0] = __float_as_uint(pb[0]);
            bf[nt][1] = __float_as_uint(pb[4]);
        }
    };

    #pragma unroll 1
    for (int c = 0; c < NCH; c++) {
        asm volatile("cp.async.wait_group 1;" ::: "memory");
        __syncthreads();
        if (c + STAGES - 1 < NCH) issue(c + STAGES - 1);
        asm volatile("cp.async.commit_group;" ::: "memory");

        const float* sA = s1 + (size_t)(c % STAGES) * (STAGE_BYTES / 4);
        const float* sB = sA + TILE_BYTES / 4;

        // software-pipelined fragment loop over 4 k8 tiles
        uint32_t a_cur[2][4], b_cur[8][2], a_nxt[2][4], b_nxt[8][2];
        load_a(a_cur, sA, 0);
        load_b(b_cur, sB, 0);
        #pragma unroll
        for (int kt = 0; kt < 4; kt++) {
            if (kt < 3) {
                load_a(a_nxt, sA, kt + 1);
                load_b(b_nxt, sB, kt + 1);
            }
            #pragma unroll
            for (int nt = 0; nt < 8; nt++) {
                mma_tf32(acc[0][nt], a_cur[0], b_cur[nt][0], b_cur[nt][1]);
                mma_tf32(acc[1][nt], a_cur[1], b_cur[nt][0], b_cur[nt][1]);
            }
            if (kt < 3) {
                #pragma unroll
                for (int mt = 0; mt < 2; mt++)
                    #pragma unroll
                    for (int q = 0; q < 4; q++) a_cur[mt][q] = a_nxt[mt][q];
                #pragma unroll
                for (int nt = 0; nt < 8; nt++) {
                    b_cur[nt][0] = b_nxt[nt][0];
                    b_cur[nt][1] = b_nxt[nt][1];
                }
            }
        }
    }

    // epilogue
    #pragma unroll
    for (int mt = 0; mt < 2; mt++) {
        int r0 = row0 + wm * 32 + mt * 16 + g;
        #pragma unroll
        for (int nt = 0; nt < 8; nt++) {
            int colb = wn * 64 + nt * 8 + tg * 2;
            if (r0 < N_NODES)
                *reinterpret_cast<float2*>(H + (size_t)r0 * DH + colb) =
                    make_float2(acc[mt][nt][0], acc[mt][nt][1]);
            if (r0 + 8 < N_NODES)
                *reinterpret_cast<float2*>(H + (size_t)(r0 + 8) * DH + colb) =
                    make_float2(acc[mt][nt][2], acc[mt][nt][3]);
        }
    }
}

// ---------------- Agg1: a1 = relu(A_hat @ h1 + b1), warp per node ----------------
// plain loop (compiler unrolls & batches loads — do NOT hand-prefetch, R6 lesson)
__global__ void agg1_kernel(const float* __restrict__ b1) {
    int gw = (blockIdx.x * blockDim.x + threadIdx.x) >> 5;
    int lane = threadIdx.x & 31;
    if (gw >= N_NODES) return;
    int beg = g_off[gw], end = g_off[gw + 1];
    float4 acc = make_float4(0.f, 0.f, 0.f, 0.f);
    for (int p = beg; p < end; ++p) {
        int2  e = g_csr[p];
        float w = __int_as_float(e.y);
        float4 hv = *reinterpret_cast<const float4*>(g_h1 + (size_t)e.x * DH + lane * 4);
        acc.x += w * hv.x; acc.y += w * hv.y; acc.z += w * hv.z; acc.w += w * hv.w;
    }
    float4 bv = *reinterpret_cast<const float4*>(b1 + lane * 4);
    acc.x = fmaxf(acc.x + bv.x, 0.f);
    acc.y = fmaxf(acc.y + bv.y, 0.f);
    acc.z = fmaxf(acc.z + bv.z, 0.f);
    acc.w = fmaxf(acc.w + bv.w, 0.f);
    *reinterpret_cast<float4*>(g_a1 + (size_t)gw * DH + lane * 4) = acc;
}

// ---------------- GEMM2: h2 = a1 @ W2 via mma.sync tf32 --------------------------
#define G2_SMEM ((128 * 132 + 40 * 132) * 4)
__global__ __launch_bounds__(128) void gemm2_tf32_kernel() {
    extern __shared__ float s2[];
    float* sA = s2;                 // [128][132]
    float* sB = s2 + 128 * 132;     // [40][132]
    const int tid  = threadIdx.x;
    const int row0 = blockIdx.x * 128;

    #pragma unroll
    for (int i = 0; i < 32; i++) {
        int idx = tid + i * 128, row = idx >> 5, kq = idx & 31;
        int gr = row0 + row;
        float4 v = (gr < N_NODES)
            ? *reinterpret_cast<const float4*>(g_a1 + (size_t)gr * DH + kq * 4)
            : make_float4(0.f, 0.f, 0.f, 0.f);
        v.x = tf32r(v.x); v.y = tf32r(v.y); v.z = tf32r(v.z); v.w = tf32r(v.w);
        *reinterpret_cast<float4*>(sA + row * 132 + kq * 4) = v;
    }
    #pragma unroll
    for (int i = 0; i < 10; i++) {
        int idx = tid + i * 128, row = idx >> 5, kq = idx & 31;
        float4 v = *reinterpret_cast<const float4*>(g_w2t + (size_t)row * DH + kq * 4);
        *reinterpret_cast<float4*>(sB + row * 132 + kq * 4) = v;
    }
    __syncthreads();

    const int wid = tid >> 5, lane = tid & 31;
    const int g = lane >> 2, tg = lane & 3;

    float acc[2][5][4];
    #pragma unroll
    for (int a = 0; a < 2; a++)
        #pragma unroll
        for (int b = 0; b < 5; b++)
            #pragma unroll
            for (int c = 0; c < 4; c++) acc[a][b][c] = 0.f;

    #pragma unroll
    for (int kt = 0; kt < DH / 8; kt++) {
        const int kk = kt * 8;
        uint32_t a[2][4];
        #pragma unroll
        for (int mt = 0; mt < 2; mt++) {
            const float* pa = sA + (wid * 32 + mt * 16 + g) * 132 + kk + tg;
            a[mt][0] = __float_as_uint(pa[0]);
            a[mt][1] = __float_as_uint(pa[8 * 132]);
            a[mt][2] = __float_as_uint(pa[4]);
            a[mt][3] = __float_as_uint(pa[8 * 132 + 4]);
        }
        #pragma unroll
        for (int nt = 0; nt < 5; nt++) {
            const float* pb = sB + (nt * 8 + g) * 132 + kk + tg;
            uint32_t b0 = __float_as_uint(pb[0]);
            uint32_t b1 = __float_as_uint(pb[4]);
            mma_tf32(acc[0][nt], a[0], b0, b1);
            mma_tf32(acc[1][nt], a[1], b0, b1);
        }
    }

    #pragma unroll
    for (int mt = 0; mt < 2; mt++) {
        int r0 = row0 + wid * 32 + mt * 16 + g;
        #pragma unroll
        for (int nt = 0; nt < 5; nt++) {
            int colb = nt * 8 + tg * 2;
            if (r0 < N_NODES)
                *reinterpret_cast<float2*>(g_h2 + (size_t)r0 * DOUT + colb) =
                    make_float2(acc[mt][nt][0], acc[mt][nt][1]);
            if (r0 + 8 < N_NODES)
                *reinterpret_cast<float2*>(g_h2 + (size_t)(r0 + 8) * DOUT + colb) =
                    make_float2(acc[mt][nt][2], acc[mt][nt][3]);
        }
    }
}

// ---------------- Agg2 + b2 + log_softmax fused, warp per node -------------------
__global__ void agg2_lsm_kernel(const float* __restrict__ b2, float* __restrict__ out,
                                int do_lsm) {
    int gw = (blockIdx.x * blockDim.x + threadIdx.x) >> 5;
    int lane = threadIdx.x & 31;
    if (gw >= N_NODES) return;
    int beg = g_off[gw], end = g_off[gw + 1];
    float acc0 = 0.f, acc1 = 0.f;
    bool has2 = lane < (DOUT - 32);
    for (int p = beg; p < end; ++p) {
        int2  e = g_csr[p];
        float w = __int_as_float(e.y);
        const float* row = g_h2 + (size_t)e.x * DOUT;
        acc0 += w * row[lane];
        if (has2) acc1 += w * row[32 + lane];
    }
    acc0 += b2[lane];
    if (has2) acc1 += b2[32 + lane];

    float* orow = out + (size_t)gw * DOUT;
    orow[lane] = acc0;
    if (has2) orow[32 + lane] = acc1;

    if (do_lsm) {
        float m = fmaxf(acc0, has2 ? acc1 : -INFINITY);
        #pragma unroll
        for (int o = 16; o > 0; o >>= 1) m = fmaxf(m, __shfl_xor_sync(0xffffffffu, m, o));
        float e = expf(acc0 - m) + (has2 ? expf(acc1 - m) : 0.f);
        #pragma unroll
        for (int o = 16; o > 0; o >>= 1) e += __shfl_xor_sync(0xffffffffu, e, o);
        float lse = m + logf(e);
        float* lrow = out + (size_t)N_NODES * DOUT + (size_t)gw * DOUT;
        lrow[lane] = acc0 - lse;
        if (has2) lrow[32 + lane] = acc1 - lse;
    }
}

// ---------------- launch --------------------------------------------------------
extern "C" void kernel_launch(void* const* d_in, const int* in_sizes, int n_in,
                              void* d_out, int out_size) {
    const float* x   = (const float*)d_in[0];
    const int*   ei  = (const int*)  d_in[1];   // [2,E] row-major
    const float* W1  = (const float*)d_in[2];
    const float* b1  = (const float*)d_in[3];
    const float* W2  = (const float*)d_in[4];
    const float* b2  = (const float*)d_in[5];
    float* out = (float*)d_out;

    const int* src = ei;
    const int* dst = ei + N_EDGES;

    float* h1;  cudaGetSymbolAddress((void**)&h1, g_h1);

    cudaFuncSetAttribute(gemm1_tf32_kernel, cudaFuncAttributeMaxDynamicSharedMemorySize,
                         G1_SMEM);
    cudaFuncSetAttribute(gemm2_tf32_kernel, cudaFuncAttributeMaxDynamicSharedMemorySize,
                         G2_SMEM);

    // gemm1 kept as 4th launch (profiled by the fixed -s window)
    init_kernel<<<(N_NODES + 255) / 256, 256>>>();                         // 1
    hist_kernel<<<(N_EDGES + 255) / 256, 256>>>(dst);                      // 2
    wt_kernel<<<dim3(4, 17), dim3(32, 32)>>>(W1, W2);                      // 3
    gemm1_tf32_kernel<<<(N_NODES + 127) / 128, 256, G1_SMEM>>>(x, h1);     // 4 <- profile
    scan_kernel<<<1, 1024>>>();                                            // 5
    scatter_kernel<<<(TOT_EDGES + 255) / 256, 256>>>(src, dst);            // 6
    agg1_kernel<<<(N_NODES * 32 + 255) / 256, 256>>>(b1);                  // 7
    gemm2_tf32_kernel<<<(N_NODES + 127) / 128, 128, G2_SMEM>>>();          // 8
    int do_lsm = (out_size >= 2 * N_NODES * DOUT) ? 1 : 0;
    agg2_lsm_kernel<<<(N_NODES * 32 + 255) / 256, 256>>>(b2, out, do_lsm); // 9
}

// round 8
// speedup vs baseline: 1.5821x; 1.1373x over previous
#include <cuda_runtime.h>
#include <cuda_fp16.h>
#include <math.h>
#include <stdint.h>

#define N_NODES 100000
#define N_EDGES 1600000
#define DIN 512
#define DH 128
#define DOUT 40
#define TOT_EDGES (N_EDGES + N_NODES)

// ---------------- scratch (device globals; no runtime allocation) -------------
__device__ int   g_deg[N_NODES];
__device__ int   g_off[N_NODES + 1];
__device__ int   g_cur[N_NODES];
__device__ float g_dinv[N_NODES];
__device__ __align__(16) int2   g_csr[TOT_EDGES];               // (src, w bits)
__device__ __align__(16) __half g_h1h[(size_t)N_NODES * DH];    // X @ W1 (fp16)
__device__ __align__(16) __half g_a1h[(size_t)N_NODES * DH];    // relu(agg+b1) (fp16)
__device__ __align__(16) __half g_h2h[(size_t)N_NODES * DOUT];  // a1 @ W2 (fp16)
__device__ __align__(16) float  g_w1tf[(size_t)DH * DIN];       // W1^T tf32, MMA-frag layout
__device__ __align__(16) float  g_w2t[(size_t)DOUT * DH];       // W2^T tf32, [n][k]

// ---------------- helpers -------------------------------------------------------
__device__ __forceinline__ uint32_t smem_u32(const void* p) {
    uint32_t a;
    asm("{ .reg .u64 t; cvta.to.shared.u64 t, %1; cvt.u32.u64 %0, t; }" : "=r"(a) : "l"(p));
    return a;
}

__device__ __forceinline__ float tf32r(float x) {
    uint32_t u;
    asm("cvt.rna.tf32.f32 %0, %1;" : "=r"(u) : "f"(x));
    return __uint_as_float(u);
}

__device__ __forceinline__ uint32_t tf32u(float x) {
    uint32_t u;
    asm("cvt.rna.tf32.f32 %0, %1;" : "=r"(u) : "f"(x));
    return u;
}

__device__ __forceinline__ void mma_tf32(float* c, const uint32_t* a, uint32_t b0, uint32_t b1) {
    asm volatile(
        "mma.sync.aligned.m16n8k8.row.col.f32.tf32.tf32.f32 "
        "{%0,%1,%2,%3}, {%4,%5,%6,%7}, {%8,%9}, {%0,%1,%2,%3};"
        : "+f"(c[0]), "+f"(c[1]), "+f"(c[2]), "+f"(c[3])
        : "r"(a[0]), "r"(a[1]), "r"(a[2]), "r"(a[3]), "r"(b0), "r"(b1));
}

// ---------------- degree init / histogram -------------------------------------
__global__ void init_kernel() {
    int i = blockIdx.x * blockDim.x + threadIdx.x;
    if (i < N_NODES) g_deg[i] = 1;   // 1 = self-loop
}

__global__ void hist_kernel(const int* __restrict__ dst) {
    int e = blockIdx.x * blockDim.x + threadIdx.x;
    if (e < N_EDGES) atomicAdd(&g_deg[dst[e]], 1);
}

// ---------------- W^T tf32 precompute (fused W1 + W2) ---------------------------
// W1 -> g_w1tf in MMA fragment layout:
//   slot((c,kt,n,tg,half)) = ((c*4+kt)*128 + n)*8 + tg*2 + half
//   holds W1[k][n] with k = c*32 + kt*8 + half*4 + tg
__global__ void wt_kernel(const float* __restrict__ W1, const float* __restrict__ W2) {
    if (blockIdx.y < 16) {
        __shared__ float t[32][33];
        const int n0 = blockIdx.x * 32, k0 = blockIdx.y * 32;
        t[threadIdx.y][threadIdx.x] = W1[(size_t)(k0 + threadIdx.y) * DH + n0 + threadIdx.x];
        __syncthreads();
        float v = t[threadIdx.x][threadIdx.y];     // = W1[k0+tx][n0+ty]
        int n = n0 + threadIdx.y, k = k0 + threadIdx.x;
        int c = k >> 5, kt = (k >> 3) & 3, j = k & 7;
        g_w1tf[((size_t)(c * 4 + kt) * 128 + n) * 8 + (j & 3) * 2 + (j >> 2)] = tf32r(v);
    } else if (blockIdx.x == 0) {
        int tid = threadIdx.y * 32 + threadIdx.x;
        for (int idx = tid; idx < DH * DOUT; idx += 1024) {
            int k = idx / DOUT, n = idx % DOUT;
            g_w2t[(size_t)n * DH + k] = tf32r(W2[idx]);
        }
    }
}

// single-block exclusive scan of g_deg -> g_off (+ g_cur), plus dinv = rsqrt(deg)
__global__ void scan_kernel() {
    __shared__ int wsum[32];
    __shared__ int chunk_total;
    const int tid = threadIdx.x;
    const int lane = tid & 31, wp = tid >> 5;
    int carry = 0;
    for (int base = 0; base < N_NODES; base += 1024) {
        int i = base + tid;
        int v = (i < N_NODES) ? g_deg[i] : 0;
        int x = v;
        #pragma unroll
        for (int o = 1; o < 32; o <<= 1) {
            int t = __shfl_up_sync(0xffffffffu, x, o);
            if (lane >= o) x += t;
        }
        if (lane == 31) wsum[wp] = x;
        __syncthreads();
        if (wp == 0) {
            int s = wsum[lane];
            int y = s;
            #pragma unroll
            for (int o = 1; o < 32; o <<= 1) {
                int t = __shfl_up_sync(0xffffffffu, y, o);
                if (lane >= o) y += t;
            }
            wsum[lane] = y - s;
            if (lane == 31) chunk_total = y;
        }
        __syncthreads();
        int incl = x + wsum[wp];
        if (i < N_NODES) {
            int off = carry + incl - v;
            g_off[i] = off;
            g_cur[i] = off;
            g_dinv[i] = rsqrtf((float)v);
        }
        carry += chunk_total;
        __syncthreads();
    }
    if (tid == 0) g_off[N_NODES] = carry;
}

__global__ void scatter_kernel(const int* __restrict__ src, const int* __restrict__ dst) {
    int e = blockIdx.x * blockDim.x + threadIdx.x;
    if (e >= TOT_EDGES) return;
    int s, d;
    if (e < N_EDGES) { s = src[e]; d = dst[e]; }
    else             { s = d = e - N_EDGES; }
    int pos = atomicAdd(&g_cur[d], 1);
    g_csr[pos] = make_int2(s, __float_as_int(g_dinv[s] * g_dinv[d]));
}

// ---------------- GEMM1: h1 = X @ W1, tf32 MMA + 3-stage cp.async ---------------
#define NCH 16
#define STAGES 3
#define A_STRIDE 36                           // A floats per row (pad 32 -> 36)
#define A_TILE_F (128 * A_STRIDE)             // 4608 floats
#define B_TILE_F 4096                         // fragment-layout B tile (no padding)
#define STAGE_F (A_TILE_F + B_TILE_F)         // 8704 floats
#define G1_SMEM (STAGES * STAGE_F * 4)        // 104448 B

__global__ __launch_bounds__(256) void gemm1_tf32_kernel(const float* __restrict__ X) {
    extern __shared__ float s1[];
    const uint32_t sbase = smem_u32(s1);
    const int tid  = threadIdx.x;
    const int row0 = blockIdx.x * 128;

    const int ldrow = tid >> 3;
    const int ldkq  = tid & 7;

    // issue cp.async loads for chunk c into its stage buffer
    auto issue = [&](int c) {
        const int s = c % STAGES;
        const uint32_t sa = sbase + s * (STAGE_F * 4);
        const uint32_t sb = sa + A_TILE_F * 4;
        const int k0 = c * 32;
        #pragma unroll
        for (int j = 0; j < 4; j++) {
            const int row = ldrow + j * 32;
            const int gr  = row0 + row;
            const int zn  = (gr < N_NODES) ? 16 : 0;
            const float* ga = X + (size_t)(gr < N_NODES ? gr : 0) * DIN + k0 + ldkq * 4;
            asm volatile("cp.async.cg.shared.global [%0], [%1], 16, %2;"
                         :: "r"(sa + row * (A_STRIDE * 4) + ldkq * 16), "l"(ga), "r"(zn));
        }
        // B tile: contiguous 16KB copy of fragment-layout chunk
        const float* gbase = g_w1tf + (size_t)c * B_TILE_F;
        #pragma unroll
        for (int j = 0; j < 4; j++) {
            const int fo = (tid + j * 256) * 4;
            asm volatile("cp.async.cg.shared.global [%0], [%1], 16;"
                         :: "r"(sb + fo * 4), "l"(gbase + fo));
        }
    };

    issue(0);
    asm volatile("cp.async.commit_group;" ::: "memory");
    issue(1);
    asm volatile("cp.async.commit_group;" ::: "memory");

    const int wid = tid >> 5, lane = tid & 31;
    const int wm = wid & 3, wn = wid >> 2;
    const int g = lane >> 2, tg = lane & 3;

    float acc[2][8][4];
    #pragma unroll
    for (int a = 0; a < 2; a++)
        #pragma unroll
        for (int b = 0; b < 8; b++)
            #pragma unroll
            for (int c = 0; c < 4; c++) acc[a][b][c] = 0.f;

    #pragma unroll 1
    for (int c = 0; c < NCH; c++) {
        asm volatile("cp.async.wait_group 1;" ::: "memory");
        __syncthreads();
        if (c + STAGES - 1 < NCH) issue(c + STAGES - 1);
        asm volatile("cp.async.commit_group;" ::: "memory");

        const float* sA = s1 + (size_t)(c % STAGES) * STAGE_F;
        const float* sB = sA + A_TILE_F;

        #pragma unroll
        for (int kt = 0; kt < 4; kt++) {
            const int kk = kt * 8;
            uint32_t a[2][4];
            #pragma unroll
            for (int mt = 0; mt < 2; mt++) {
                const float* pa = sA + (wm * 32 + mt * 16 + g) * A_STRIDE + kk + tg;
                a[mt][0] = tf32u(pa[0]);
                a[mt][1] = tf32u(pa[8 * A_STRIDE]);
                a[mt][2] = tf32u(pa[4]);
                a[mt][3] = tf32u(pa[8 * A_STRIDE + 4]);
            }
            #pragma unroll
            for (int nt = 0; nt < 8; nt++) {
                const float2 b = *reinterpret_cast<const float2*>(
                    sB + kt * 1024 + (wn * 64 + nt * 8 + g) * 8 + tg * 2);
                uint32_t b0 = __float_as_uint(b.x);
                uint32_t b1 = __float_as_uint(b.y);
                mma_tf32(acc[0][nt], a[0], b0, b1);
                mma_tf32(acc[1][nt], a[1], b0, b1);
            }
        }
    }

    // epilogue -> fp16
    #pragma unroll
    for (int mt = 0; mt < 2; mt++) {
        int r0 = row0 + wm * 32 + mt * 16 + g;
        #pragma unroll
        for (int nt = 0; nt < 8; nt++) {
            int colb = wn * 64 + nt * 8 + tg * 2;
            if (r0 < N_NODES)
                *reinterpret_cast<__half2*>(g_h1h + (size_t)r0 * DH + colb) =
                    __floats2half2_rn(acc[mt][nt][0], acc[mt][nt][1]);
            if (r0 + 8 < N_NODES)
                *reinterpret_cast<__half2*>(g_h1h + (size_t)(r0 + 8) * DH + colb) =
                    __floats2half2_rn(acc[mt][nt][2], acc[mt][nt][3]);
        }
    }
}

// ---------------- Agg1: a1 = relu(A_hat @ h1 + b1), warp per node ----------------
// plain loop (compiler unrolls & batches loads); fp16 gather halves L2 traffic
__global__ void agg1_kernel(const float* __restrict__ b1) {
    int gw = (blockIdx.x * blockDim.x + threadIdx.x) >> 5;
    int lane = threadIdx.x & 31;
    if (gw >= N_NODES) return;
    int beg = g_off[gw], end = g_off[gw + 1];
    float4 acc = make_float4(0.f, 0.f, 0.f, 0.f);
    for (int p = beg; p < end; ++p) {
        int2  e = g_csr[p];
        float w = __int_as_float(e.y);
        uint2 hv = __ldcg(reinterpret_cast<const uint2*>(g_h1h + (size_t)e.x * DH) + lane);
        float2 f0 = __half22float2(*reinterpret_cast<__half2*>(&hv.x));
        float2 f1 = __half22float2(*reinterpret_cast<__half2*>(&hv.y));
        acc.x += w * f0.x; acc.y += w * f0.y; acc.z += w * f1.x; acc.w += w * f1.y;
    }
    float4 bv = *reinterpret_cast<const float4*>(b1 + lane * 4);
    __half2 o0 = __floats2half2_rn(fmaxf(acc.x + bv.x, 0.f), fmaxf(acc.y + bv.y, 0.f));
    __half2 o1 = __floats2half2_rn(fmaxf(acc.z + bv.z, 0.f), fmaxf(acc.w + bv.w, 0.f));
    uint2 st;
    st.x = *reinterpret_cast<uint32_t*>(&o0);
    st.y = *reinterpret_cast<uint32_t*>(&o1);
    *(reinterpret_cast<uint2*>(g_a1h + (size_t)gw * DH) + lane) = st;
}

// ---------------- GEMM2: h2 = a1 @ W2 via mma.sync tf32 --------------------------
#define G2_SMEM ((128 * 132 + 40 * 132) * 4)
__global__ __launch_bounds__(128) void gemm2_tf32_kernel() {
    extern __shared__ float s2[];
    float* sA = s2;                 // [128][132]
    float* sB = s2 + 128 * 132;     // [40][132]
    const int tid  = threadIdx.x;
    const int row0 = blockIdx.x * 128;

    #pragma unroll
    for (int i = 0; i < 32; i++) {
        int idx = tid + i * 128, row = idx >> 5, q = idx & 31;
        int gr = row0 + row;
        uint2 hv = make_uint2(0u, 0u);
        if (gr < N_NODES)
            hv = *(reinterpret_cast<const uint2*>(g_a1h + (size_t)gr * DH) + q);
        float2 f0 = __half22float2(*reinterpret_cast<__half2*>(&hv.x));
        float2 f1 = __half22float2(*reinterpret_cast<__half2*>(&hv.y));
        float4 v = make_float4(tf32r(f0.x), tf32r(f0.y), tf32r(f1.x), tf32r(f1.y));
        *reinterpret_cast<float4*>(sA + row * 132 + q * 4) = v;
    }
    #pragma unroll
    for (int i = 0; i < 10; i++) {
        int idx = tid + i * 128, row = idx >> 5, kq = idx & 31;
        float4 v = *reinterpret_cast<const float4*>(g_w2t + (size_t)row * DH + kq * 4);
        *reinterpret_cast<float4*>(sB + row * 132 + kq * 4) = v;
    }
    __syncthreads();

    const int wid = tid >> 5, lane = tid & 31;
    const int g = lane >> 2, tg = lane & 3;

    float acc[2][5][4];
    #pragma unroll
    for (int a = 0; a < 2; a++)
        #pragma unroll
        for (int b = 0; b < 5; b++)
            #pragma unroll
            for (int c = 0; c < 4; c++) acc[a][b][c] = 0.f;

    #pragma unroll
    for (int kt = 0; kt < DH / 8; kt++) {
        const int kk = kt * 8;
        uint32_t a[2][4];
        #pragma unroll
        for (int mt = 0; mt < 2; mt++) {
            const float* pa = sA + (wid * 32 + mt * 16 + g) * 132 + kk + tg;
            a[mt][0] = __float_as_uint(pa[0]);
            a[mt][1] = __float_as_uint(pa[8 * 132]);
            a[mt][2] = __float_as_uint(pa[4]);
            a[mt][3] = __float_as_uint(pa[8 * 132 + 4]);
        }
        #pragma unroll
        for (int nt = 0; nt < 5; nt++) {
            const float* pb = sB + (nt * 8 + g) * 132 + kk + tg;
            uint32_t b0 = __float_as_uint(pb[0]);
            uint32_t b1 = __float_as_uint(pb[4]);
            mma_tf32(acc[0][nt], a[0], b0, b1);
            mma_tf32(acc[1][nt], a[1], b0, b1);
        }
    }

    #pragma unroll
    for (int mt = 0; mt < 2; mt++) {
        int r0 = row0 + wid * 32 + mt * 16 + g;
        #pragma unroll
        for (int nt = 0; nt < 5; nt++) {
            int colb = nt * 8 + tg * 2;
            if (r0 < N_NODES)
                *reinterpret_cast<__half2*>(g_h2h + (size_t)r0 * DOUT + colb) =
                    __floats2half2_rn(acc[mt][nt][0], acc[mt][nt][1]);
            if (r0 + 8 < N_NODES)
                *reinterpret_cast<__half2*>(g_h2h + (size_t)(r0 + 8) * DOUT + colb) =
                    __floats2half2_rn(acc[mt][nt][2], acc[mt][nt][3]);
        }
    }
}

// ---------------- Agg2 + b2 + log_softmax fused, warp per node -------------------
// lanes 0..19 each own 2 of the 40 output features (fp16 gather)
__global__ void agg2_lsm_kernel(const float* __restrict__ b2, float* __restrict__ out,
                                int do_lsm) {
    int gw = (blockIdx.x * blockDim.x + threadIdx.x) >> 5;
    int lane = threadIdx.x & 31;
    if (gw >= N_NODES) return;
    int beg = g_off[gw], end = g_off[gw + 1];
    const bool act = lane < (DOUT / 2);
    float acc0 = 0.f, acc1 = 0.f;
    for (int p = beg; p < end; ++p) {
        int2  e = g_csr[p];
        float w = __int_as_float(e.y);
        if (act) {
            uint32_t hv = __ldcg(reinterpret_cast<const uint32_t*>(
                g_h2h + (size_t)e.x * DOUT) + lane);
            float2 f = __half22float2(*reinterpret_cast<__half2*>(&hv));
            acc0 += w * f.x;
            acc1 += w * f.y;
        }
    }
    if (act) {
        acc0 += b2[lane * 2];
        acc1 += b2[lane * 2 + 1];
        *reinterpret_cast<float2*>(out + (size_t)gw * DOUT + lane * 2) =
            make_float2(acc0, acc1);
    }
    if (do_lsm) {
        float m = act ? fmaxf(acc0, acc1) : -INFINITY;
        #pragma unroll
        for (int o = 16; o > 0; o >>= 1) m = fmaxf(m, __shfl_xor_sync(0xffffffffu, m, o));
        float e = act ? (expf(acc0 - m) + expf(acc1 - m)) : 0.f;
        #pragma unroll
        for (int o = 16; o > 0; o >>= 1) e += __shfl_xor_sync(0xffffffffu, e, o);
        float lse = m + logf(e);
        if (act) {
            float* lrow = out + (size_t)N_NODES * DOUT + (size_t)gw * DOUT;
            *reinterpret_cast<float2*>(lrow + lane * 2) =
                make_float2(acc0 - lse, acc1 - lse);
        }
    }
}

// ---------------- launch --------------------------------------------------------
extern "C" void kernel_launch(void* const* d_in, const int* in_sizes, int n_in,
                              void* d_out, int out_size) {
    const float* x   = (const float*)d_in[0];
    const int*   ei  = (const int*)  d_in[1];   // [2,E] row-major
    const float* W1  = (const float*)d_in[2];
    const float* b1  = (const float*)d_in[3];
    const float* W2  = (const float*)d_in[4];
    const float* b2  = (const float*)d_in[5];
    float* out = (float*)d_out;

    const int* src = ei;
    const int* dst = ei + N_EDGES;

    cudaFuncSetAttribute(gemm1_tf32_kernel, cudaFuncAttributeMaxDynamicSharedMemorySize,
                         G1_SMEM);
    cudaFuncSetAttribute(gemm2_tf32_kernel, cudaFuncAttributeMaxDynamicSharedMemorySize,
                         G2_SMEM);

    // gemm1 kept as 4th launch (profiled by the fixed -s window)
    init_kernel<<<(N_NODES + 255) / 256, 256>>>();                         // 1
    hist_kernel<<<(N_EDGES + 255) / 256, 256>>>(dst);                      // 2
    wt_kernel<<<dim3(4, 17), dim3(32, 32)>>>(W1, W2);                      // 3
    gemm1_tf32_kernel<<<(N_NODES + 127) / 128, 256, G1_SMEM>>>(x);         // 4 <- profile
    scan_kernel<<<1, 1024>>>();                                            // 5
    scatter_kernel<<<(TOT_EDGES + 255) / 256, 256>>>(src, dst);            // 6
    agg1_kernel<<<(N_NODES * 32 + 255) / 256, 256>>>(b1);                  // 7
    gemm2_tf32_kernel<<<(N_NODES + 127) / 128, 128, G2_SMEM>>>();          // 8
    int do_lsm = (out_size >= 2 * N_NODES * DOUT) ? 1 : 0;
    agg2_lsm_kernel<<<(N_NODES * 32 + 255) / 256, 256>>>(b2, out, do_lsm); // 9
}

// round 9
// speedup vs baseline: 1.7446x; 1.1027x over previous
#include <cuda_runtime.h>
#include <cuda_fp16.h>
#include <math.h>
#include <stdint.h>

#define N_NODES 100000
#define N_EDGES 1600000
#define DIN 512
#define DH 128
#define DOUT 40
#define TOT_EDGES (N_EDGES + N_NODES)

// ---------------- scratch (device globals; no runtime allocation) -------------
__device__ int   g_deg[N_NODES];
__device__ int   g_off[N_NODES + 1];
__device__ int   g_cur[N_NODES];
__device__ float g_dinv[N_NODES];
__device__ __align__(16) int2   g_csr[TOT_EDGES];               // (src, w bits)
__device__ __align__(16) __half g_h1h[(size_t)N_NODES * DH];    // X @ W1 (fp16)
__device__ __align__(16) __half g_a1h[(size_t)N_NODES * DH];    // relu(agg+b1) (fp16)
__device__ __align__(16) __half g_h2h[(size_t)N_NODES * DOUT];  // a1 @ W2 (fp16)
__device__ __align__(16) __half g_w1hf[(size_t)DH * DIN];       // W1 fp16, B-fragment layout
__device__ __align__(16) float  g_w2t[(size_t)DOUT * DH];       // W2^T tf32, [n][k]

// ---------------- helpers -------------------------------------------------------
__device__ __forceinline__ uint32_t smem_u32(const void* p) {
    uint32_t a;
    asm("{ .reg .u64 t; cvta.to.shared.u64 t, %1; cvt.u32.u64 %0, t; }" : "=r"(a) : "l"(p));
    return a;
}

__device__ __forceinline__ float tf32r(float x) {
    uint32_t u;
    asm("cvt.rna.tf32.f32 %0, %1;" : "=r"(u) : "f"(x));
    return __uint_as_float(u);
}

__device__ __forceinline__ uint32_t packh2(float2 v) {
    __half2 h = __floats2half2_rn(v.x, v.y);
    return *reinterpret_cast<uint32_t*>(&h);
}

__device__ __forceinline__ void mma_f16(float* c, const uint32_t* a, uint32_t b0, uint32_t b1) {
    asm volatile(
        "mma.sync.aligned.m16n8k16.row.col.f32.f16.f16.f32 "
        "{%0,%1,%2,%3}, {%4,%5,%6,%7}, {%8,%9}, {%0,%1,%2,%3};"
        : "+f"(c[0]), "+f"(c[1]), "+f"(c[2]), "+f"(c[3])
        : "r"(a[0]), "r"(a[1]), "r"(a[2]), "r"(a[3]), "r"(b0), "r"(b1));
}

__device__ __forceinline__ void mma_tf32(float* c, const uint32_t* a, uint32_t b0, uint32_t b1) {
    asm volatile(
        "mma.sync.aligned.m16n8k8.row.col.f32.tf32.tf32.f32 "
        "{%0,%1,%2,%3}, {%4,%5,%6,%7}, {%8,%9}, {%0,%1,%2,%3};"
        : "+f"(c[0]), "+f"(c[1]), "+f"(c[2]), "+f"(c[3])
        : "r"(a[0]), "r"(a[1]), "r"(a[2]), "r"(a[3]), "r"(b0), "r"(b1));
}

// ---------------- degree init / histogram -------------------------------------
__global__ void init_kernel() {
    int i = blockIdx.x * blockDim.x + threadIdx.x;
    if (i < N_NODES) g_deg[i] = 1;   // 1 = self-loop
}

__global__ void hist_kernel(const int* __restrict__ dst) {
    int e = blockIdx.x * blockDim.x + threadIdx.x;
    if (e < N_EDGES) atomicAdd(&g_deg[dst[e]], 1);
}

// ---------------- W precompute (fused W1 fp16-frag + W2 tf32) -------------------
// W1[k][n] -> g_w1hf in m16n8k16 B-fragment layout:
//   c = k>>5, kt = (k>>4)&1, q = k&15
//   slot = ((c*2+kt)*128 + n)*16 + ((q&7)>>1)*4 + ((q>>3)&1)*2 + (q&1)
__global__ void wt_kernel(const float* __restrict__ W1, const float* __restrict__ W2) {
    if (blockIdx.y < 16) {
        const int n0 = blockIdx.x * 32, k0 = blockIdx.y * 32;
        const int n = n0 + threadIdx.x, k = k0 + threadIdx.y;
        float v = W1[(size_t)k * DH + n];
        int c = k >> 5, kt = (k >> 4) & 1, q = k & 15;
        size_t slot = ((size_t)(c * 2 + kt) * 128 + n) * 16
                      + ((q & 7) >> 1) * 4 + ((q >> 3) & 1) * 2 + (q & 1);
        g_w1hf[slot] = __float2half_rn(v);
    } else if (blockIdx.x == 0) {
        int tid = threadIdx.y * 32 + threadIdx.x;
        for (int idx = tid; idx < DH * DOUT; idx += 1024) {
            int k = idx / DOUT, n = idx % DOUT;
            g_w2t[(size_t)n * DH + k] = tf32r(W2[idx]);
        }
    }
}

// single-block exclusive scan of g_deg -> g_off (+ g_cur), plus dinv = rsqrt(deg)
__global__ void scan_kernel() {
    __shared__ int wsum[32];
    __shared__ int chunk_total;
    const int tid = threadIdx.x;
    const int lane = tid & 31, wp = tid >> 5;
    int carry = 0;
    for (int base = 0; base < N_NODES; base += 1024) {
        int i = base + tid;
        int v = (i < N_NODES) ? g_deg[i] : 0;
        int x = v;
        #pragma unroll
        for (int o = 1; o < 32; o <<= 1) {
            int t = __shfl_up_sync(0xffffffffu, x, o);
            if (lane >= o) x += t;
        }
        if (lane == 31) wsum[wp] = x;
        __syncthreads();
        if (wp == 0) {
            int s = wsum[lane];
            int y = s;
            #pragma unroll
            for (int o = 1; o < 32; o <<= 1) {
                int t = __shfl_up_sync(0xffffffffu, y, o);
                if (lane >= o) y += t;
            }
            wsum[lane] = y - s;
            if (lane == 31) chunk_total = y;
        }
        __syncthreads();
        int incl = x + wsum[wp];
        if (i < N_NODES) {
            int off = carry + incl - v;
            g_off[i] = off;
            g_cur[i] = off;
            g_dinv[i] = rsqrtf((float)v);
        }
        carry += chunk_total;
        __syncthreads();
    }
    if (tid == 0) g_off[N_NODES] = carry;
}

__global__ void scatter_kernel(const int* __restrict__ src, const int* __restrict__ dst) {
    int e = blockIdx.x * blockDim.x + threadIdx.x;
    if (e >= TOT_EDGES) return;
    int s, d;
    if (e < N_EDGES) { s = src[e]; d = dst[e]; }
    else             { s = d = e - N_EDGES; }
    int pos = atomicAdd(&g_cur[d], 1);
    g_csr[pos] = make_int2(s, __float_as_int(g_dinv[s] * g_dinv[d]));
}

// ---------------- GEMM1: h1 = X @ W1, fp16 MMA (m16n8k16) + 3-stage cp.async -----
#define NCH 16
#define STAGES 3
#define A_STRIDE 40                            // A floats per row (pad 32 -> 40)
#define A_TILE_F (128 * A_STRIDE)              // 5120 floats = 20480 B
#define B_TILE_H 4096                          // fragment-layout fp16 tile (8192 B)
#define STAGE_B (A_TILE_F * 4 + B_TILE_H * 2)  // 28672 B
#define G1_SMEM (STAGES * STAGE_B)             // 86016 B

__global__ __launch_bounds__(256) void gemm1_f16_kernel(const float* __restrict__ X) {
    extern __shared__ float s1[];
    const uint32_t sbase = smem_u32(s1);
    const int tid  = threadIdx.x;
    const int row0 = blockIdx.x * 128;

    const int ldrow = tid >> 3;
    const int ldkq  = tid & 7;

    // issue cp.async loads for chunk c into its stage buffer
    auto issue = [&](int c) {
        const int s = c % STAGES;
        const uint32_t sa = sbase + s * STAGE_B;
        const uint32_t sb = sa + A_TILE_F * 4;
        const int k0 = c * 32;
        #pragma unroll
        for (int j = 0; j < 4; j++) {
            const int row = ldrow + j * 32;
            const int gr  = row0 + row;
            const int zn  = (gr < N_NODES) ? 16 : 0;
            const float* ga = X + (size_t)(gr < N_NODES ? gr : 0) * DIN + k0 + ldkq * 4;
            asm volatile("cp.async.cg.shared.global [%0], [%1], 16, %2;"
                         :: "r"(sa + row * (A_STRIDE * 4) + ldkq * 16), "l"(ga), "r"(zn));
        }
        // B tile: contiguous 8KB copy of fragment-layout fp16 chunk
        const __half* gb = g_w1hf + (size_t)c * B_TILE_H;
        asm volatile("cp.async.cg.shared.global [%0], [%1], 16;"
                     :: "r"(sb + tid * 32), "l"(reinterpret_cast<const char*>(gb) + tid * 32));
        asm volatile("cp.async.cg.shared.global [%0], [%1], 16;"
                     :: "r"(sb + tid * 32 + 16),
                        "l"(reinterpret_cast<const char*>(gb) + tid * 32 + 16));
    };

    issue(0);
    asm volatile("cp.async.commit_group;" ::: "memory");
    issue(1);
    asm volatile("cp.async.commit_group;" ::: "memory");

    const int wid = tid >> 5, lane = tid & 31;
    const int wm = wid & 3, wn = wid >> 2;
    const int g = lane >> 2, tg = lane & 3;

    float acc[2][8][4];
    #pragma unroll
    for (int a = 0; a < 2; a++)
        #pragma unroll
        for (int b = 0; b < 8; b++)
            #pragma unroll
            for (int c = 0; c < 4; c++) acc[a][b][c] = 0.f;

    #pragma unroll 1
    for (int c = 0; c < NCH; c++) {
        asm volatile("cp.async.wait_group 1;" ::: "memory");
        __syncthreads();
        if (c + STAGES - 1 < NCH) issue(c + STAGES - 1);
        asm volatile("cp.async.commit_group;" ::: "memory");

        const float*  sA = s1 + (size_t)(c % STAGES) * (STAGE_B / 4);
        const __half* sB = reinterpret_cast<const __half*>(sA + A_TILE_F);

        #pragma unroll
        for (int kt = 0; kt < 2; kt++) {
            uint32_t a[2][4];
            #pragma unroll
            for (int mt = 0; mt < 2; mt++) {
                const float2* pa = reinterpret_cast<const float2*>(
                    sA + (wm * 32 + mt * 16 + g) * A_STRIDE + kt * 16 + tg * 2);
                const float2* pa8 = pa + 4 * A_STRIDE;   // +8 rows
                float2 v00 = pa[0],  v10 = pa[4];
                float2 v01 = pa8[0], v11 = pa8[4];
                a[mt][0] = packh2(v00);
                a[mt][1] = packh2(v01);
                a[mt][2] = packh2(v10);
                a[mt][3] = packh2(v11);
            }
            #pragma unroll
            for (int nt = 0; nt < 8; nt++) {
                const uint2 b = *reinterpret_cast<const uint2*>(
                    sB + (size_t)kt * 2048 + (wn * 64 + nt * 8 + g) * 16 + tg * 4);
                mma_f16(acc[0][nt], a[0], b.x, b.y);
                mma_f16(acc[1][nt], a[1], b.x, b.y);
            }
        }
    }

    // epilogue -> fp16
    #pragma unroll
    for (int mt = 0; mt < 2; mt++) {
        int r0 = row0 + wm * 32 + mt * 16 + g;
        #pragma unroll
        for (int nt = 0; nt < 8; nt++) {
            int colb = wn * 64 + nt * 8 + tg * 2;
            if (r0 < N_NODES)
                *reinterpret_cast<__half2*>(g_h1h + (size_t)r0 * DH + colb) =
                    __floats2half2_rn(acc[mt][nt][0], acc[mt][nt][1]);
            if (r0 + 8 < N_NODES)
                *reinterpret_cast<__half2*>(g_h1h + (size_t)(r0 + 8) * DH + colb) =
                    __floats2half2_rn(acc[mt][nt][2], acc[mt][nt][3]);
        }
    }
}

// ---------------- Agg1: a1 = relu(A_hat @ h1 + b1), warp per node ----------------
__global__ void agg1_kernel(const float* __restrict__ b1) {
    int gw = (blockIdx.x * blockDim.x + threadIdx.x) >> 5;
    int lane = threadIdx.x & 31;
    if (gw >= N_NODES) return;
    int beg = g_off[gw], end = g_off[gw + 1];
    float4 acc = make_float4(0.f, 0.f, 0.f, 0.f);
    for (int p = beg; p < end; ++p) {
        int2  e = g_csr[p];
        float w = __int_as_float(e.y);
        uint2 hv = __ldcg(reinterpret_cast<const uint2*>(g_h1h + (size_t)e.x * DH) + lane);
        float2 f0 = __half22float2(*reinterpret_cast<__half2*>(&hv.x));
        float2 f1 = __half22float2(*reinterpret_cast<__half2*>(&hv.y));
        acc.x += w * f0.x; acc.y += w * f0.y; acc.z += w * f1.x; acc.w += w * f1.y;
    }
    float4 bv = *reinterpret_cast<const float4*>(b1 + lane * 4);
    __half2 o0 = __floats2half2_rn(fmaxf(acc.x + bv.x, 0.f), fmaxf(acc.y + bv.y, 0.f));
    __half2 o1 = __floats2half2_rn(fmaxf(acc.z + bv.z, 0.f), fmaxf(acc.w + bv.w, 0.f));
    uint2 st;
    st.x = *reinterpret_cast<uint32_t*>(&o0);
    st.y = *reinterpret_cast<uint32_t*>(&o1);
    *(reinterpret_cast<uint2*>(g_a1h + (size_t)gw * DH) + lane) = st;
}

// ---------------- GEMM2: h2 = a1 @ W2 via mma.sync tf32 --------------------------
#define G2_SMEM ((128 * 132 + 40 * 132) * 4)
__global__ __launch_bounds__(128) void gemm2_tf32_kernel() {
    extern __shared__ float s2[];
    float* sA = s2;                 // [128][132]
    float* sB = s2 + 128 * 132;     // [40][132]
    const int tid  = threadIdx.x;
    const int row0 = blockIdx.x * 128;

    #pragma unroll
    for (int i = 0; i < 32; i++) {
        int idx = tid + i * 128, row = idx >> 5, q = idx & 31;
        int gr = row0 + row;
        uint2 hv = make_uint2(0u, 0u);
        if (gr < N_NODES)
            hv = *(reinterpret_cast<const uint2*>(g_a1h + (size_t)gr * DH) + q);
        float2 f0 = __half22float2(*reinterpret_cast<__half2*>(&hv.x));
        float2 f1 = __half22float2(*reinterpret_cast<__half2*>(&hv.y));
        float4 v = make_float4(tf32r(f0.x), tf32r(f0.y), tf32r(f1.x), tf32r(f1.y));
        *reinterpret_cast<float4*>(sA + row * 132 + q * 4) = v;
    }
    #pragma unroll
    for (int i = 0; i < 10; i++) {
        int idx = tid + i * 128, row = idx >> 5, kq = idx & 31;
        float4 v = *reinterpret_cast<const float4*>(g_w2t + (size_t)row * DH + kq * 4);
        *reinterpret_cast<float4*>(sB + row * 132 + kq * 4) = v;
    }
    __syncthreads();

    const int wid = tid >> 5, lane = tid & 31;
    const int g = lane >> 2, tg = lane & 3;

    float acc[2][5][4];
    #pragma unroll
    for (int a = 0; a < 2; a++)
        #pragma unroll
        for (int b = 0; b < 5; b++)
            #pragma unroll
            for (int c = 0; c < 4; c++) acc[a][b][c] = 0.f;

    #pragma unroll
    for (int kt = 0; kt < DH / 8; kt++) {
        const int kk = kt * 8;
        uint32_t a[2][4];
        #pragma unroll
        for (int mt = 0; mt < 2; mt++) {
            const float* pa = sA + (wid * 32 + mt * 16 + g) * 132 + kk + tg;
            a[mt][0] = __float_as_uint(pa[0]);
            a[mt][1] = __float_as_uint(pa[8 * 132]);
            a[mt][2] = __float_as_uint(pa[4]);
            a[mt][3] = __float_as_uint(pa[8 * 132 + 4]);
        }
        #pragma unroll
        for (int nt = 0; nt < 5; nt++) {
            const float* pb = sB + (nt * 8 + g) * 132 + kk + tg;
            uint32_t b0 = __float_as_uint(pb[0]);
            uint32_t b1 = __float_as_uint(pb[4]);
            mma_tf32(acc[0][nt], a[0], b0, b1);
            mma_tf32(acc[1][nt], a[1], b0, b1);
        }
    }

    #pragma unroll
    for (int mt = 0; mt < 2; mt++) {
        int r0 = row0 + wid * 32 + mt * 16 + g;
        #pragma unroll
        for (int nt = 0; nt < 5; nt++) {
            int colb = nt * 8 + tg * 2;
            if (r0 < N_NODES)
                *reinterpret_cast<__half2*>(g_h2h + (size_t)r0 * DOUT + colb) =
                    __floats2half2_rn(acc[mt][nt][0], acc[mt][nt][1]);
            if (r0 + 8 < N_NODES)
                *reinterpret_cast<__half2*>(g_h2h + (size_t)(r0 + 8) * DOUT + colb) =
                    __floats2half2_rn(acc[mt][nt][2], acc[mt][nt][3]);
        }
    }
}

// ---------------- Agg2 + b2 + log_softmax fused, warp per node -------------------
__global__ void agg2_lsm_kernel(const float* __restrict__ b2, float* __restrict__ out,
                                int do_lsm) {
    int gw = (blockIdx.x * blockDim.x + threadIdx.x) >> 5;
    int lane = threadIdx.x & 31;
    if (gw >= N_NODES) return;
    int beg = g_off[gw], end = g_off[gw + 1];
    const bool act = lane < (DOUT / 2);
    float acc0 = 0.f, acc1 = 0.f;
    for (int p = beg; p < end; ++p) {
        int2  e = g_csr[p];
        float w = __int_as_float(e.y);
        if (act) {
            uint32_t hv = __ldcg(reinterpret_cast<const uint32_t*>(
                g_h2h + (size_t)e.x * DOUT) + lane);
            float2 f = __half22float2(*reinterpret_cast<__half2*>(&hv));
            acc0 += w * f.x;
            acc1 += w * f.y;
        }
    }
    if (act) {
        acc0 += b2[lane * 2];
        acc1 += b2[lane * 2 + 1];
        *reinterpret_cast<float2*>(out + (size_t)gw * DOUT + lane * 2) =
            make_float2(acc0, acc1);
    }
    if (do_lsm) {
        float m = act ? fmaxf(acc0, acc1) : -INFINITY;
        #pragma unroll
        for (int o = 16; o > 0; o >>= 1) m = fmaxf(m, __shfl_xor_sync(0xffffffffu, m, o));
        float e = act ? (expf(acc0 - m) + expf(acc1 - m)) : 0.f;
        #pragma unroll
        for (int o = 16; o > 0; o >>= 1) e += __shfl_xor_sync(0xffffffffu, e, o);
        float lse = m + logf(e);
        if (act) {
            float* lrow = out + (size_t)N_NODES * DOUT + (size_t)gw * DOUT;
            *reinterpret_cast<float2*>(lrow + lane * 2) =
                make_float2(acc0 - lse, acc1 - lse);
        }
    }
}

// ---------------- launch --------------------------------------------------------
extern "C" void kernel_launch(void* const* d_in, const int* in_sizes, int n_in,
                              void* d_out, int out_size) {
    const float* x   = (const float*)d_in[0];
    const int*   ei  = (const int*)  d_in[1];   // [2,E] row-major
    const float* W1  = (const float*)d_in[2];
    const float* b1  = (const float*)d_in[3];
    const float* W2  = (const float*)d_in[4];
    const float* b2  = (const float*)d_in[5];
    float* out = (float*)d_out;

    const int* src = ei;
    const int* dst = ei + N_EDGES;

    cudaFuncSetAttribute(gemm1_f16_kernel, cudaFuncAttributeMaxDynamicSharedMemorySize,
                         G1_SMEM);
    cudaFuncSetAttribute(gemm2_tf32_kernel, cudaFuncAttributeMaxDynamicSharedMemorySize,
                         G2_SMEM);

    // gemm1 kept as 4th launch (profiled by the fixed -s window)
    init_kernel<<<(N_NODES + 255) / 256, 256>>>();                         // 1
    hist_kernel<<<(N_EDGES + 255) / 256, 256>>>(dst);                      // 2
    wt_kernel<<<dim3(4, 17), dim3(32, 32)>>>(W1, W2);                      // 3
    gemm1_f16_kernel<<<(N_NODES + 127) / 128, 256, G1_SMEM>>>(x);          // 4 <- profile
    scan_kernel<<<1, 1024>>>();                                            // 5
    scatter_kernel<<<(TOT_EDGES + 255) / 256, 256>>>(src, dst);            // 6
    agg1_kernel<<<(N_NODES * 32 + 255) / 256, 256>>>(b1);                  // 7
    gemm2_tf32_kernel<<<(N_NODES + 127) / 128, 128, G2_SMEM>>>();          // 8
    int do_lsm = (out_size >= 2 * N_NODES * DOUT) ? 1 : 0;
    agg2_lsm_kernel<<<(N_NODES * 32 + 255) / 256, 256>>>(b2, out, do_lsm); // 9
}